// round 7
// baseline (speedup 1.0000x reference)
#include <cuda_runtime.h>
#include <math.h>
#include <stdint.h>

#define NLAYER 8
#define DMODEL 512
#define DINNER 1024
#define DSTATE 16
#define DCONV  4
#define DTRANK 32
#define BATCH  8
#define SEQ    800
#define MROWS  (BATCH*SEQ)   // 6400

// ---------------- scratch (static device globals: allowed; no runtime alloc) ----
__device__ float g_pin [MROWS*1024];
__device__ float g_xt  [MROWS*DMODEL];
__device__ float g_xz  [MROWS*2*DINNER];
__device__ float g_xcf [MROWS*DINNER];
__device__ float g_xcb [MROWS*DINNER];
__device__ float g_prjf[MROWS*64];
__device__ float g_prjb[MROWS*64];
__device__ float g_dtf [MROWS*DINNER];
__device__ float g_dtb [MROWS*DINNER];
__device__ float g_yf  [MROWS*DINNER];
__device__ float g_yb  [MROWS*DINNER];
__device__ float g_t512[MROWS*DMODEL];
__device__ float g_mid [MROWS*DINNER];

// ---------------- epilogue ids ----------------
#define EPI_NONE     0
#define EPI_BIAS     1
#define EPI_SOFTPLUS 2
#define EPI_GELU     3

__device__ __forceinline__ float silu_f(float x) {
    return x * (1.0f / (1.0f + __expf(-x)));
}

// ---------------- double-buffered register-tiled SGEMM -------------------------
// C[M,N] = A[M,K] (optionally + A2) @ B[K,N]  (+bias / softplus / gelu epilogue)
// Requires M%BM==0, N%BN==0, K%BK==0 (true for every call in this model).
template<int BM, int BN, int BK, int TM, int TN, int EPI, bool SUMA>
__global__ __launch_bounds__((BM/TM)*(BN/TN))
void sgemm_k(const float* __restrict__ A, const float* __restrict__ A2, int lda,
             const float* __restrict__ Bw, int ldb,
             const float* __restrict__ bias,
             float* __restrict__ C, int ldc, int K)
{
    constexpr int NT = (BM/TM)*(BN/TN);
    constexpr int LA = BM*BK/(4*NT);   // float4 A-loads per thread
    constexpr int LB = BK*BN/(4*NT);   // float4 B-loads per thread
    static_assert(LA >= 1 && LB >= 1, "tile too small");

    __shared__ float As[2][BK][BM];
    __shared__ float Bs[2][BK][BN];

    const int tid = threadIdx.x;
    const int tx  = tid % (BN/TN);
    const int ty  = tid / (BN/TN);
    const int m0  = blockIdx.y * BM;
    const int n0  = blockIdx.x * BN;

    float acc[TM][TN];
#pragma unroll
    for (int i = 0; i < TM; i++)
#pragma unroll
        for (int j = 0; j < TN; j++) acc[i][j] = 0.0f;

    float4 ra[LA], rb[LB];

    auto fetchA = [&](int k0) {
#pragma unroll
        for (int i = 0; i < LA; i++) {
            int q  = tid + i*NT;
            int r  = q / (BK/4);
            int c4 = q % (BK/4);
            float4 v = *reinterpret_cast<const float4*>(
                A + (size_t)(m0 + r)*lda + k0 + c4*4);
            if (SUMA) {
                float4 w = *reinterpret_cast<const float4*>(
                    A2 + (size_t)(m0 + r)*lda + k0 + c4*4);
                v.x += w.x; v.y += w.y; v.z += w.z; v.w += w.w;
            }
            ra[i] = v;
        }
    };
    auto fetchB = [&](int k0) {
#pragma unroll
        for (int i = 0; i < LB; i++) {
            int q  = tid + i*NT;
            int r  = q / (BN/4);
            int c4 = q % (BN/4);
            rb[i] = *reinterpret_cast<const float4*>(
                Bw + (size_t)(k0 + r)*ldb + n0 + c4*4);
        }
    };
    auto stage = [&](int buf) {
#pragma unroll
        for (int i = 0; i < LA; i++) {
            int q  = tid + i*NT;
            int r  = q / (BK/4);
            int c4 = q % (BK/4);
            As[buf][c4*4+0][r] = ra[i].x; As[buf][c4*4+1][r] = ra[i].y;
            As[buf][c4*4+2][r] = ra[i].z; As[buf][c4*4+3][r] = ra[i].w;
        }
#pragma unroll
        for (int i = 0; i < LB; i++) {
            int q  = tid + i*NT;
            int r  = q / (BN/4);
            int c4 = q % (BN/4);
            *reinterpret_cast<float4*>(&Bs[buf][r][c4*4]) = rb[i];
        }
    };
    auto compute = [&](int buf) {
#pragma unroll
        for (int kk = 0; kk < BK; kk++) {
            float fa[TM], fb[TN];
#pragma unroll
            for (int i = 0; i < TM; i++) fa[i] = As[buf][kk][ty*TM + i];
#pragma unroll
            for (int j = 0; j < TN; j++) fb[j] = Bs[buf][kk][tx*TN + j];
#pragma unroll
            for (int i = 0; i < TM; i++)
#pragma unroll
                for (int j = 0; j < TN; j++)
                    acc[i][j] = fmaf(fa[i], fb[j], acc[i][j]);
        }
    };

    // prologue: stage tile 0
    fetchA(0); fetchB(0);
    stage(0);
    __syncthreads();

    int buf = 0;
    for (int k0 = BK; k0 < K; k0 += BK) {
        fetchA(k0); fetchB(k0);   // global loads in flight during compute
        compute(buf);
        stage(buf ^ 1);
        __syncthreads();
        buf ^= 1;
    }
    compute(buf);

#pragma unroll
    for (int i = 0; i < TM; i++) {
        int m = m0 + ty*TM + i;
#pragma unroll
        for (int j = 0; j < TN; j++) {
            int n = n0 + tx*TN + j;
            float v = acc[i][j];
            if (EPI == EPI_BIAS || EPI == EPI_SOFTPLUS || EPI == EPI_GELU)
                v += bias[n];
            if (EPI == EPI_SOFTPLUS)
                v = (v > 0.0f) ? (v + log1pf(__expf(-v))) : log1pf(__expf(v));
            if (EPI == EPI_GELU)
                v = 0.5f * v * (1.0f + erff(v * 0.70710678118654752f));
            C[(size_t)m*ldc + n] = v;
        }
    }
}

template<int BM, int BN, int BK, int TM, int TN, int EPI, bool SUMA>
static void launch_gemm(const float* A, const float* A2, int lda,
                        const float* Bw, int ldb, const float* bias,
                        float* C, int ldc, int M, int N, int K)
{
    dim3 grid(N/BN, M/BM);
    sgemm_k<BM,BN,BK,TM,TN,EPI,SUMA><<<grid, (BM/TM)*(BN/TN)>>>(
        A, A2, lda, Bw, ldb, bias, C, ldc, K);
}

// ---------------- patch gather ------------------------------------------------
// x: (B,1,32,160,160). Output row r=b*800+t (t=f*100+h*10+w), col k=p1*64+p2*4+pf.
__global__ void gather_k(const float* __restrict__ x, float* __restrict__ pin)
{
    int idx = blockIdx.x * blockDim.x + threadIdx.x;
    if (idx >= MROWS*1024) return;
    int k   = idx & 1023;
    int row = idx >> 10;
    int b = row / SEQ, t = row % SEQ;
    int f = t / 100, rem = t % 100;
    int hh = rem / 10, ww = rem % 10;
    int p1 = k >> 6;
    int r2 = k & 63;
    int p2 = r2 >> 2;
    int pf = r2 & 3;
    size_t src = (((size_t)b*32 + (f*4 + pf))*160 + (hh*16 + p1))*160 + (ww*16 + p2);
    pin[idx] = x[src];
}

// ---------------- depthwise causal conv (fwd + reversed) + SiLU ---------------
__global__ void conv_k(const float* __restrict__ xz,
                       const float* __restrict__ wf, const float* __restrict__ bf,
                       const float* __restrict__ wb, const float* __restrict__ bb,
                       float* __restrict__ xcf, float* __restrict__ xcb)
{
    int idx = blockIdx.x * blockDim.x + threadIdx.x;
    if (idx >= MROWS*DINNER) return;
    int d   = idx & (DINNER-1);
    int row = idx >> 10;
    int b = row / SEQ, t = row % SEQ;
    const float* base = xz + (size_t)b*SEQ*2048 + d;   // stride 2048 over time

    float w0 = wf[d*4+0], w1 = wf[d*4+1], w2 = wf[d*4+2], w3 = wf[d*4+3];
    float acc = bf[d];
    acc = fmaf(w3, base[(size_t)t*2048], acc);
    if (t >= 1) acc = fmaf(w2, base[(size_t)(t-1)*2048], acc);
    if (t >= 2) acc = fmaf(w1, base[(size_t)(t-2)*2048], acc);
    if (t >= 3) acc = fmaf(w0, base[(size_t)(t-3)*2048], acc);
    xcf[(size_t)row*DINNER + d] = silu_f(acc);

    float v0 = wb[d*4+0], v1 = wb[d*4+1], v2 = wb[d*4+2], v3 = wb[d*4+3];
    float accb = bb[d];
    accb = fmaf(v3, base[(size_t)(SEQ-1-t)*2048], accb);
    if (t >= 1) accb = fmaf(v2, base[(size_t)(SEQ-t)*2048], accb);
    if (t >= 2) accb = fmaf(v1, base[(size_t)(SEQ+1-t)*2048], accb);
    if (t >= 3) accb = fmaf(v0, base[(size_t)(SEQ+2-t)*2048], accb);
    xcb[(size_t)row*DINNER + d] = silu_f(accb);
}

// ---------------- selective-scan (both directions) ----------------------------
// One thread per (b, d): 16 states in registers, 800 sequential steps,
// software-pipelined loads (t+1 fetched before step t's dependent compute).
__global__ __launch_bounds__(128)
void scan_k(const float* __restrict__ dtf, const float* __restrict__ dtb,
            const float* __restrict__ uf,  const float* __restrict__ ub,
            const float* __restrict__ pf,  const float* __restrict__ pb,
            const float* __restrict__ Af,  const float* __restrict__ Ab,
            const float* __restrict__ Df,  const float* __restrict__ Db,
            const float* __restrict__ xz,
            float* __restrict__ yf, float* __restrict__ yb)
{
    const int d   = blockIdx.x * 128 + threadIdx.x;
    const int b   = blockIdx.y;
    const int dir = blockIdx.z;

    const float* dtp = dir ? dtb : dtf;
    const float* up  = dir ? ub  : uf;
    const float* pp  = dir ? pb  : pf;
    const float* Ap  = dir ? Ab  : Af;
    const float* Dp  = dir ? Db  : Df;
    float*       yp  = dir ? yb  : yf;

    float A[DSTATE];
#pragma unroll
    for (int n = 0; n < DSTATE; n++) A[n] = -expf(Ap[(size_t)d*DSTATE + n]);
    const float Dv = Dp[d];

    // structure check: A[n] == A[0]*(n+1)  (true for this model's A_log)
    bool fast = true;
#pragma unroll
    for (int n = 1; n < DSTATE; n++) {
        float ex = A[0] * (float)(n+1);
        fast = fast && (fabsf(A[n] - ex) <= 1e-4f * fabsf(ex) + 1e-6f);
    }

    float h[DSTATE];
#pragma unroll
    for (int n = 0; n < DSTATE; n++) h[n] = 0.0f;

    // prefetch step 0
    int row = b*SEQ;
    float dt_c = dtp[(size_t)row*DINNER + d];
    float u_c  = up [(size_t)row*DINNER + d];
    const float4* bc = reinterpret_cast<const float4*>(pp + (size_t)row*64 + 32);
    float4 Bq[4] = {bc[0], bc[1], bc[2], bc[3]};
    float4 Cq[4] = {bc[4], bc[5], bc[6], bc[7]};
    int orow0 = dir ? (b*SEQ + SEQ-1) : row;
    float z_c = xz[(size_t)orow0*2048 + DINNER + d];

    for (int t = 0; t < SEQ; t++) {
        const float dt = dt_c, u = u_c, zv = z_c;
        float Bv[16] = {Bq[0].x,Bq[0].y,Bq[0].z,Bq[0].w, Bq[1].x,Bq[1].y,Bq[1].z,Bq[1].w,
                        Bq[2].x,Bq[2].y,Bq[2].z,Bq[2].w, Bq[3].x,Bq[3].y,Bq[3].z,Bq[3].w};
        float Cv[16] = {Cq[0].x,Cq[0].y,Cq[0].z,Cq[0].w, Cq[1].x,Cq[1].y,Cq[1].z,Cq[1].w,
                        Cq[2].x,Cq[2].y,Cq[2].z,Cq[2].w, Cq[3].x,Cq[3].y,Cq[3].z,Cq[3].w};
        const int orow = dir ? (b*SEQ + (SEQ-1-t)) : (b*SEQ + t);

        // issue next step's loads before the dependent compute chain
        if (t + 1 < SEQ) {
            const int nrow = b*SEQ + t + 1;
            dt_c = dtp[(size_t)nrow*DINNER + d];
            u_c  = up [(size_t)nrow*DINNER + d];
            const float4* nbc = reinterpret_cast<const float4*>(pp + (size_t)nrow*64 + 32);
            Bq[0]=nbc[0]; Bq[1]=nbc[1]; Bq[2]=nbc[2]; Bq[3]=nbc[3];
            Cq[0]=nbc[4]; Cq[1]=nbc[5]; Cq[2]=nbc[6]; Cq[3]=nbc[7];
            const int norow = dir ? (b*SEQ + (SEQ-2-t)) : nrow;
            z_c = xz[(size_t)norow*2048 + DINNER + d];
        }

        float e[16];
        if (fast) {
            float r  = __expf(dt * A[0]);
            float r2 = r*r, r4 = r2*r2, r8 = r4*r4;
            e[0]=r;       e[1]=r2;      e[2]=r2*r;     e[3]=r4;
            e[4]=r4*r;    e[5]=r4*r2;   e[6]=r4*e[2];  e[7]=r8;
            e[8]=r8*r;    e[9]=r8*r2;   e[10]=r8*e[2]; e[11]=r8*r4;
            e[12]=r8*e[4];e[13]=r8*e[5];e[14]=r8*e[6]; e[15]=r8*r8;
        } else {
#pragma unroll
            for (int n = 0; n < 16; n++) e[n] = __expf(dt * A[n]);
        }

        const float du = dt * u;
        float a0=0.f, a1=0.f, a2=0.f, a3=0.f;
#pragma unroll
        for (int n = 0; n < 16; n += 4) {
            h[n+0] = fmaf(e[n+0], h[n+0], du * Bv[n+0]);
            h[n+1] = fmaf(e[n+1], h[n+1], du * Bv[n+1]);
            h[n+2] = fmaf(e[n+2], h[n+2], du * Bv[n+2]);
            h[n+3] = fmaf(e[n+3], h[n+3], du * Bv[n+3]);
            a0 = fmaf(h[n+0], Cv[n+0], a0);
            a1 = fmaf(h[n+1], Cv[n+1], a1);
            a2 = fmaf(h[n+2], Cv[n+2], a2);
            a3 = fmaf(h[n+3], Cv[n+3], a3);
        }
        float y = (a0+a1) + (a2+a3) + u * Dv;
        yp[(size_t)orow*DINNER + d] = y * silu_f(zv);
    }
}

// ---------------- LayerNorm(y)*g+b + residual into xt (+ optional out copy) ---
__global__ __launch_bounds__(256)
void ln_res_k(const float* __restrict__ y, const float* __restrict__ g,
              const float* __restrict__ be, float* __restrict__ xt,
              float* __restrict__ outp)
{
    const int row = blockIdx.x;
    const int tid = threadIdx.x;
    const float v0 = y[(size_t)row*DMODEL + tid];
    const float v1 = y[(size_t)row*DMODEL + 256 + tid];
    float s  = v0 + v1;
    float ss = v0*v0 + v1*v1;
#pragma unroll
    for (int off = 16; off > 0; off >>= 1) {
        s  += __shfl_xor_sync(0xffffffffu, s,  off);
        ss += __shfl_xor_sync(0xffffffffu, ss, off);
    }
    __shared__ float sh[2][8];
    const int wid = tid >> 5, lane = tid & 31;
    if (lane == 0) { sh[0][wid] = s; sh[1][wid] = ss; }
    __syncthreads();
    float ts = 0.f, tss = 0.f;
#pragma unroll
    for (int i = 0; i < 8; i++) { ts += sh[0][i]; tss += sh[1][i]; }
    const float mean = ts * (1.0f/DMODEL);
    const float var  = tss * (1.0f/DMODEL) - mean*mean;
    const float rstd = rsqrtf(var + 1e-5f);

    float o0 = (v0 - mean)*rstd*g[tid]     + be[tid]     + xt[(size_t)row*DMODEL + tid];
    float o1 = (v1 - mean)*rstd*g[256+tid] + be[256+tid] + xt[(size_t)row*DMODEL + 256 + tid];
    xt[(size_t)row*DMODEL + tid]       = o0;
    xt[(size_t)row*DMODEL + 256 + tid] = o1;
    if (outp) {
        outp[(size_t)row*DMODEL + tid]       = o0;
        outp[(size_t)row*DMODEL + 256 + tid] = o1;
    }
}

// ---------------- host orchestration ------------------------------------------
extern "C" void kernel_launch(void* const* d_in, const int* in_sizes, int n_in,
                              void* d_out, int out_size)
{
    (void)in_sizes; (void)n_in; (void)out_size;
    const float* x        = (const float*)d_in[0];
    const float* patch_w  = (const float*)d_in[1];
    const float* patch_b  = (const float*)d_in[2];
    const float* in_proj  = (const float*)d_in[3];
    const float* conv_w   = (const float*)d_in[4];
    const float* conv_b   = (const float*)d_in[5];
    const float* xproj_w  = (const float*)d_in[6];
    const float* dt_w     = (const float*)d_in[7];
    const float* dt_bias  = (const float*)d_in[8];
    const float* A_log    = (const float*)d_in[9];
    const float* D_skip   = (const float*)d_in[10];
    const float* conv_wb  = (const float*)d_in[11];
    const float* conv_bb  = (const float*)d_in[12];
    const float* xproj_wb = (const float*)d_in[13];
    const float* dt_wb    = (const float*)d_in[14];
    const float* dt_biasb = (const float*)d_in[15];
    const float* A_logb   = (const float*)d_in[16];
    const float* D_skipb  = (const float*)d_in[17];
    const float* out_proj = (const float*)d_in[18];
    const float* ln1_g    = (const float*)d_in[19];
    const float* ln1_b    = (const float*)d_in[20];
    const float* fc1_w    = (const float*)d_in[21];
    const float* fc1_b    = (const float*)d_in[22];
    const float* fc2_w    = (const float*)d_in[23];
    const float* fc2_b    = (const float*)d_in[24];
    const float* ln2_g    = (const float*)d_in[25];
    const float* ln2_b    = (const float*)d_in[26];
    float* out = (float*)d_out;

    float *pin, *xt, *xz, *xcf, *xcb, *prjf, *prjb, *dtf, *dtb, *yf, *yb, *t512, *mid;
    cudaGetSymbolAddress((void**)&pin,  g_pin);
    cudaGetSymbolAddress((void**)&xt,   g_xt);
    cudaGetSymbolAddress((void**)&xz,   g_xz);
    cudaGetSymbolAddress((void**)&xcf,  g_xcf);
    cudaGetSymbolAddress((void**)&xcb,  g_xcb);
    cudaGetSymbolAddress((void**)&prjf, g_prjf);
    cudaGetSymbolAddress((void**)&prjb, g_prjb);
    cudaGetSymbolAddress((void**)&dtf,  g_dtf);
    cudaGetSymbolAddress((void**)&dtb,  g_dtb);
    cudaGetSymbolAddress((void**)&yf,   g_yf);
    cudaGetSymbolAddress((void**)&yb,   g_yb);
    cudaGetSymbolAddress((void**)&t512, g_t512);
    cudaGetSymbolAddress((void**)&mid,  g_mid);

    const int M = MROWS;

    // patch embed
    gather_k<<<(MROWS*1024 + 255)/256, 256>>>(x, pin);
    launch_gemm<128,128,16,8,8,EPI_BIAS,false>(pin, nullptr, 1024, patch_w, 512,
                                               patch_b, xt, 512, M, 512, 1024);

    for (int l = 0; l < NLAYER; l++) {
        // in_proj: xz = xt @ W (512 x 2048)
        launch_gemm<128,128,16,8,8,EPI_NONE,false>(
            xt, nullptr, 512, in_proj + (size_t)l*512*2048, 2048,
            nullptr, xz, 2048, M, 2048, 512);

        // causal depthwise conv + silu, both directions
        conv_k<<<(MROWS*DINNER + 255)/256, 256>>>(
            xz,
            conv_w  + (size_t)l*DINNER*DCONV, conv_b  + (size_t)l*DINNER,
            conv_wb + (size_t)l*DINNER*DCONV, conv_bb + (size_t)l*DINNER,
            xcf, xcb);

        // x-proj (N=64): dti | B | C
        launch_gemm<128,64,16,8,4,EPI_NONE,false>(
            xcf, nullptr, DINNER, xproj_w + (size_t)l*DINNER*64, 64,
            nullptr, prjf, 64, M, 64, DINNER);
        launch_gemm<128,64,16,8,4,EPI_NONE,false>(
            xcb, nullptr, DINNER, xproj_wb + (size_t)l*DINNER*64, 64,
            nullptr, prjb, 64, M, 64, DINNER);

        // dt = softplus(dti @ dt_w + dt_bias), K=32
        launch_gemm<128,128,16,8,8,EPI_SOFTPLUS,false>(
            prjf, nullptr, 64, dt_w + (size_t)l*DTRANK*DINNER, DINNER,
            dt_bias + (size_t)l*DINNER, dtf, DINNER, M, DINNER, DTRANK);
        launch_gemm<128,128,16,8,8,EPI_SOFTPLUS,false>(
            prjb, nullptr, 64, dt_wb + (size_t)l*DTRANK*DINNER, DINNER,
            dt_biasb + (size_t)l*DINNER, dtb, DINNER, M, DINNER, DTRANK);

        // selective scan, both dirs, gated by silu(z), bwd un-reversed on write
        scan_k<<<dim3(DINNER/128, BATCH, 2), 128>>>(
            dtf, dtb, xcf, xcb, prjf, prjb,
            A_log  + (size_t)l*DINNER*DSTATE, A_logb + (size_t)l*DINNER*DSTATE,
            D_skip + (size_t)l*DINNER,        D_skipb + (size_t)l*DINNER,
            xz, yf, yb);

        // out_proj on (yf + yb)
        launch_gemm<128,128,16,8,8,EPI_NONE,true>(
            yf, yb, DINNER, out_proj + (size_t)l*DINNER*DMODEL, DMODEL,
            nullptr, t512, DMODEL, M, DMODEL, DINNER);

        // xt = LN1(t512) + xt
        ln_res_k<<<MROWS, 256>>>(t512, ln1_g + (size_t)l*DMODEL,
                                 ln1_b + (size_t)l*DMODEL, xt, nullptr);

        // MLP
        launch_gemm<128,128,16,8,8,EPI_GELU,false>(
            xt, nullptr, DMODEL, fc1_w + (size_t)l*DMODEL*1024, 1024,
            fc1_b + (size_t)l*1024, mid, 1024, M, 1024, DMODEL);
        launch_gemm<128,128,16,8,8,EPI_BIAS,false>(
            mid, nullptr, 1024, fc2_w + (size_t)l*1024*DMODEL, DMODEL,
            fc2_b + (size_t)l*DMODEL, t512, DMODEL, M, DMODEL, 1024);

        // xt = LN2(mlp) + xt ; also emit layer output
        ln_res_k<<<MROWS, 256>>>(t512, ln2_g + (size_t)l*DMODEL,
                                 ln2_b + (size_t)l*DMODEL, xt,
                                 out + (size_t)l*MROWS*DMODEL);
    }
}